// round 9
// baseline (speedup 1.0000x reference)
#include <cuda_runtime.h>

#define BB 32
#define TT 2048
#define CC 2048
#define EE 64
#define SEG 16
#define TCHUNK (TT / SEG)          // 128
#define C4 (CC / 4)                // 512
#define E4N (EE / 4)               // 16
#define TQ 128                     // t-rows per k23 block
#define PARTS 16
#define CPART (CC / PARTS)         // 128

#define BTE (BB * TT * EE)         // 4194304 = 2^22
#define FB_OFF  BTE                // 4194304
#define LOG_OFF (BTE + 1)          // 4194305
#define MASK_OFF (BTE + 1 + BB * EE) // 4196353 (== 1 mod 4)

// Scratch (no cudaMalloc allowed)
__device__ float g_partials[SEG * BB * CC];   // 2 MB
__device__ float g_dots[BB * PARTS * EE];     // 128 KB
__device__ float g_ssum[BB * PARTS * EE];     // 128 KB
__device__ float g_sumsq[BB * PARTS];

// ---------------------------------------------------------------------------
// Kernel 1: partial sums of hidden_states over T (split into SEG chunks).
// Plain loads (measured: __ldcs cost ~2us vs default). 86% DRAM = at HBM cap.
// ---------------------------------------------------------------------------
__global__ void k1_partial_sums(const float* __restrict__ hs, float* __restrict__ out) {
    if (blockIdx.x == 0 && blockIdx.y == 0 && blockIdx.z == 0 && threadIdx.x == 0)
        out[FB_OFF] = 0.0f;

    const int c4  = blockIdx.x * 256 + threadIdx.x;   // 0..511
    const int b   = blockIdx.y;
    const int seg = blockIdx.z;

    const float4* __restrict__ hs4 = (const float4*)hs;
    size_t base = ((size_t)b * TT + (size_t)seg * TCHUNK) * C4 + (size_t)c4;

    float4 acc = make_float4(0.f, 0.f, 0.f, 0.f);
#pragma unroll 8
    for (int t = 0; t < TCHUNK; ++t) {
        float4 v = hs4[base + (size_t)t * C4];
        acc.x += v.x; acc.y += v.y; acc.z += v.z; acc.w += v.w;
    }
    ((float4*)g_partials)[((size_t)seg * BB + b) * C4 + c4] = acc;
}

// ---------------------------------------------------------------------------
// Kernel 2a: stage-1 gating reduction. grid = (PARTS=16, BB=32) = 512 blocks.
// Block (part, b): reduces its 128-c chunk of g_partials -> partial sumsq and
// partial dot/ss vs sim for all 64 experts. Deterministic fixed-order sums.
// ---------------------------------------------------------------------------
__global__ void k2a_partial_gating(const float* __restrict__ sim) {
    __shared__ float rep_s[CPART];
    __shared__ float red[128];
    __shared__ float dots4[4][EE];
    __shared__ float ss4[4][EE];

    const int part = blockIdx.x;
    const int b    = blockIdx.y;
    const int tid  = threadIdx.x;
    const int c0   = part * CPART;

    // rep chunk + partial sumsq
    if (tid < CPART) {
        float s = 0.f;
#pragma unroll
        for (int p = 0; p < SEG; ++p)
            s += g_partials[(size_t)p * BB * CC + (size_t)b * CC + c0 + tid];
        float r = s * (1.0f / TT);
        rep_s[tid] = r;
        red[tid] = r * r;
    }
    __syncthreads();
    for (int ofs = 64; ofs > 0; ofs >>= 1) {
        if (tid < ofs) red[tid] += red[tid + ofs];
        __syncthreads();
    }
    if (tid == 0) g_sumsq[b * PARTS + part] = red[0];

    // partial dot/ss over this c-chunk: e = tid&63, 4 c-groups of 32
    const int e  = tid & (EE - 1);
    const int cg = tid >> 6;
    float dot = 0.f, ss = 0.f;
#pragma unroll 8
    for (int j = 0; j < 32; ++j) {
        int cl = cg * 32 + j;
        float sv = sim[(size_t)(c0 + cl) * EE + e];
        dot = fmaf(rep_s[cl], sv, dot);
        ss  = fmaf(sv, sv, ss);
    }
    dots4[cg][e] = dot;
    ss4[cg][e]  = ss;
    __syncthreads();

    if (tid < EE) {
        g_dots[(size_t)(b * PARTS + part) * EE + tid] =
            dots4[0][tid] + dots4[1][tid] + dots4[2][tid] + dots4[3][tid];
        g_ssum[(size_t)(b * PARTS + part) * EE + tid] =
            ss4[0][tid] + ss4[1][tid] + ss4[2][tid] + ss4[3][tid];
    }
}

// ---------------------------------------------------------------------------
// Kernel 2b+3: grid = (BB, TT/TQ) = (32, 16), 256 threads. NO producer/
// consumer sync: every block redundantly finishes the gating for its b from
// the stage-1 partials (~8 KB of L2-hit loads, fixed order -> bit-identical
// across blocks -> deterministic), then broadcasts its TQ-row chunk.
// Only yc==0 writes logits / fallback count.
// ---------------------------------------------------------------------------
__global__ void k23_gating_broadcast(const float* __restrict__ gates,
                                     float* __restrict__ out) {
    __shared__ float logits_s[EE];
    __shared__ float msk[EE];
    __shared__ float probs_s[EE];

    const int b   = blockIdx.x;
    const int yc  = blockIdx.y;
    const int tid = threadIdx.x;

    // ---- finish gating (redundant per block) ----
    float l = 0.f;
    if (tid < EE) {
        float dot = 0.f, ss = 0.f, sq = 0.f;
#pragma unroll
        for (int p = 0; p < PARTS; ++p) {
            dot += g_dots[(size_t)(b * PARTS + p) * EE + tid];
            ss  += g_ssum[(size_t)(b * PARTS + p) * EE + tid];
            sq  += g_sumsq[b * PARTS + p];          // uniform -> L2 broadcast
        }
        float nrep = fmaxf(sqrtf(sq), 1e-12f);
        float ncol = fmaxf(sqrtf(ss), 1e-12f);
        float aff  = dot / (nrep * ncol);
        float gv   = gates[tid];
        float sig  = 1.0f / (1.0f + __expf(-gv));
        l = aff - sig;
        logits_s[tid] = l;
    }

    // activity count (block-wide popcount + barrier; logits_s now visible)
    const int na = __syncthreads_count((tid < EE) && (l > 0.f));
    const int inactive = (na == 0) ? 1 : 0;

    // mask: threshold or top-32 fallback (lax.top_k tie semantics: stable,
    // lowest index wins among equals)
    if (tid < EE) {
        float m;
        if (!inactive) {
            m = (l > 0.f) ? 1.f : 0.f;
        } else {
            int rank = 0;
            for (int j = 0; j < EE; ++j) {
                float lj = logits_s[j];
                rank += ((lj > l) || (lj == l && j < tid)) ? 1 : 0;
            }
            m = (rank < (EE / 2)) ? 1.f : 0.f;
        }
        msk[tid] = m;
    }
    __syncthreads();

    // masked softmax: redundant per-thread scan over 64 smem entries
    float mx = -3.402823466e+38f;
#pragma unroll
    for (int e = 0; e < EE; ++e)
        if (msk[e] > 0.f) mx = fmaxf(mx, fmaxf(logits_s[e], 0.f));
    float sum = 0.f;
#pragma unroll
    for (int e = 0; e < EE; ++e)
        if (msk[e] > 0.f) sum += __expf(fmaxf(logits_s[e], 0.f) - mx);

    if (tid < EE) {
        float gated = fmaxf(l, 0.f);
        probs_s[tid] = (msk[tid] > 0.f) ? (__expf(gated - mx) / sum) : 0.f;
        if (yc == 0) out[LOG_OFF + b * EE + tid] = l;   // logits written once
    }
    if (yc == 0 && tid == 0 && inactive)
        atomicAdd(&out[FB_OFF], 1.0f);  // integer-valued -> deterministic
    __syncthreads();

    // ================= broadcast chunk [yc*TQ, yc*TQ+TQ) =================
    const int slot = tid & 15;   // 0..15
    const int trow = tid >> 4;   // 0..15

    const float4 pv = ((const float4*)probs_s)[slot];

    // mask values per slot: slot 0 -> scalars e=0,1,2,63 ; slot s>0 ->
    // aligned float4 at e=4s-1 (MASK_OFF == 1 mod 4)
    float4 mv = make_float4(0.f, 0.f, 0.f, 0.f);
    float m0 = 0.f, m1 = 0.f, m2 = 0.f, m63 = 0.f;
    if (slot == 0) { m0 = msk[0]; m1 = msk[1]; m2 = msk[2]; m63 = msk[63]; }
    else { int e = 4 * slot - 1; mv = make_float4(msk[e], msk[e+1], msk[e+2], msk[e+3]); }

    const size_t brow = (size_t)b * TT * EE;
    const int t0 = yc * TQ;

#pragma unroll
    for (int it = 0; it < TQ / 16; ++it) {
        const size_t row = brow + (size_t)(t0 + it * 16 + trow) * EE;
        __stcs((float4*)(out) + row / 4 + slot, pv);
        if (slot == 0) {
            float* d = out + MASK_OFF + row;
            __stcs(d + 0, m0); __stcs(d + 1, m1); __stcs(d + 2, m2); __stcs(d + 63, m63);
        } else {
            __stcs((float4*)(out + MASK_OFF + row + 4 * slot - 1), mv);
        }
    }
}

// ---------------------------------------------------------------------------
extern "C" void kernel_launch(void* const* d_in, const int* in_sizes, int n_in,
                              void* d_out, int out_size) {
    const float* hs    = (const float*)d_in[0];
    const float* sim   = (const float*)d_in[1];
    const float* gates = (const float*)d_in[2];
    float* out = (float*)d_out;

    k1_partial_sums<<<dim3(C4 / 256, BB, SEG), 256>>>(hs, out);
    k2a_partial_gating<<<dim3(PARTS, BB), 256>>>(sim);
    k23_gating_broadcast<<<dim3(BB, TT / TQ), 256>>>(gates, out);
}

// round 10
// speedup vs baseline: 1.0051x; 1.0051x over previous
#include <cuda_runtime.h>

#define BB 32
#define TT 2048
#define CC 2048
#define EE 64
#define SEG 16
#define TCHUNK (TT / SEG)          // 128
#define C4 (CC / 4)                // 512
#define E4N (EE / 4)               // 16
#define TQ 128                     // t-rows per k3 block
#define PARTS 16
#define CPART (CC / PARTS)         // 128

#define BTE (BB * TT * EE)         // 4194304 = 2^22
#define FB_OFF  BTE                // 4194304
#define LOG_OFF (BTE + 1)          // 4194305
#define MASK_OFF (BTE + 1 + BB * EE) // 4196353 (== 1 mod 4)

// Scratch (no cudaMalloc allowed)
__device__ float g_partials[SEG * BB * CC];   // 2 MB
__device__ float g_dots[BB * PARTS * EE];     // 128 KB
__device__ float g_ssum[BB * PARTS * EE];     // 128 KB
__device__ float g_sumsq[BB * PARTS];
__device__ float g_probs_seq[BB * EE];
__device__ float g_mask_seq[BB * EE];
__device__ int   g_cnt[BB];

// ---------------------------------------------------------------------------
// Kernel 1: partial sums of hidden_states over T (split into SEG chunks).
// Plain loads (measured best). 85% DRAM = at HBM/LTS cap. Resets counters.
// ---------------------------------------------------------------------------
__global__ void k1_partial_sums(const float* __restrict__ hs, float* __restrict__ out) {
    if (blockIdx.x == 0 && blockIdx.y == 0 && blockIdx.z == 0) {
        if (threadIdx.x == 0) out[FB_OFF] = 0.0f;
        if (threadIdx.x < BB) g_cnt[threadIdx.x] = 0;
    }

    const int c4  = blockIdx.x * 256 + threadIdx.x;   // 0..511
    const int b   = blockIdx.y;
    const int seg = blockIdx.z;

    const float4* __restrict__ hs4 = (const float4*)hs;
    size_t base = ((size_t)b * TT + (size_t)seg * TCHUNK) * C4 + (size_t)c4;

    float4 acc = make_float4(0.f, 0.f, 0.f, 0.f);
#pragma unroll 8
    for (int t = 0; t < TCHUNK; ++t) {
        float4 v = hs4[base + (size_t)t * C4];
        acc.x += v.x; acc.y += v.y; acc.z += v.z; acc.w += v.w;
    }
    ((float4*)g_partials)[((size_t)seg * BB + b) * C4 + c4] = acc;
}

// ---------------------------------------------------------------------------
// Kernel 2: stage-1 gating reduction + last-block-per-b finish.
// grid = (PARTS=16, BB=32) = 512 blocks, 256 threads.
// Block (part, b): reduces its 128-c chunk of g_partials -> partial sumsq and
// partial dot/ss vs sim for all 64 experts (fixed-order, deterministic).
// The LAST arriving block for each b (atomic counter) re-reads all 16 fixed-
// order partials and finishes: logits, mask (+top-32 fallback), softmax,
// writes g_probs_seq / g_mask_seq / logits / fallback count.
// ---------------------------------------------------------------------------
__global__ void k2_gating(const float* __restrict__ sim,
                          const float* __restrict__ gates,
                          float* __restrict__ out) {
    __shared__ float rep_s[CPART];
    __shared__ float red[128];
    __shared__ float dots4[4][EE];
    __shared__ float ss4[4][EE];
    __shared__ int   s_last;
    __shared__ float logits_s[EE];
    __shared__ float msk[EE];
    __shared__ float sm_max, sm_sum;

    const int part = blockIdx.x;
    const int b    = blockIdx.y;
    const int tid  = threadIdx.x;
    const int c0   = part * CPART;

    // ---- stage 1: rep chunk + partial sumsq ----
    if (tid < CPART) {
        float s = 0.f;
#pragma unroll
        for (int p = 0; p < SEG; ++p)
            s += g_partials[(size_t)p * BB * CC + (size_t)b * CC + c0 + tid];
        float r = s * (1.0f / TT);
        rep_s[tid] = r;
        red[tid] = r * r;
    }
    __syncthreads();
    for (int ofs = 64; ofs > 0; ofs >>= 1) {
        if (tid < ofs) red[tid] += red[tid + ofs];
        __syncthreads();
    }
    if (tid == 0) g_sumsq[b * PARTS + part] = red[0];

    // partial dot/ss over this c-chunk: e = tid&63, 4 c-groups of 32
    const int e  = tid & (EE - 1);
    const int cg = tid >> 6;
    float dot = 0.f, ss = 0.f;
#pragma unroll 8
    for (int j = 0; j < 32; ++j) {
        int cl = cg * 32 + j;
        float sv = sim[(size_t)(c0 + cl) * EE + e];
        dot = fmaf(rep_s[cl], sv, dot);
        ss  = fmaf(sv, sv, ss);
    }
    dots4[cg][e] = dot;
    ss4[cg][e]  = ss;
    __syncthreads();

    if (tid < EE) {
        g_dots[(size_t)(b * PARTS + part) * EE + tid] =
            dots4[0][tid] + dots4[1][tid] + dots4[2][tid] + dots4[3][tid];
        g_ssum[(size_t)(b * PARTS + part) * EE + tid] =
            ss4[0][tid] + ss4[1][tid] + ss4[2][tid] + ss4[3][tid];
    }

    // ---- last-block election ----
    __threadfence();
    __syncthreads();
    if (tid == 0) s_last = (atomicAdd(&g_cnt[b], 1) == PARTS - 1) ? 1 : 0;
    __syncthreads();
    if (!s_last) return;

    // ---- finish (exactly one block per b; fixed-order -> deterministic) ----
    float l = 0.f;
    if (tid < EE) {
        float d = 0.f, s2 = 0.f, sq = 0.f;
#pragma unroll
        for (int p = 0; p < PARTS; ++p) {
            d  += g_dots[(size_t)(b * PARTS + p) * EE + tid];
            s2 += g_ssum[(size_t)(b * PARTS + p) * EE + tid];
            sq += g_sumsq[b * PARTS + p];          // uniform -> broadcast
        }
        float nrep = fmaxf(sqrtf(sq), 1e-12f);
        float ncol = fmaxf(sqrtf(s2), 1e-12f);
        float aff  = d / (nrep * ncol);
        float gv   = gates[tid];
        float sig  = 1.0f / (1.0f + __expf(-gv));
        l = aff - sig;
        logits_s[tid] = l;
    }
    const int na = __syncthreads_count((tid < EE) && (l > 0.f));
    const int inactive = (na == 0) ? 1 : 0;

    // mask: threshold or top-32 fallback (lax.top_k tie semantics: stable,
    // lowest index wins among equals)
    if (tid < EE) {
        float m;
        if (!inactive) {
            m = (l > 0.f) ? 1.f : 0.f;
        } else {
            int rank = 0;
            for (int j = 0; j < EE; ++j) {
                float lj = logits_s[j];
                rank += ((lj > l) || (lj == l && j < tid)) ? 1 : 0;
            }
            m = (rank < (EE / 2)) ? 1.f : 0.f;
        }
        msk[tid] = m;
    }
    __syncthreads();

    if (tid == 0) {
        float mx = -3.402823466e+38f;
        for (int i = 0; i < EE; ++i)
            if (msk[i] > 0.f) mx = fmaxf(mx, fmaxf(logits_s[i], 0.f));
        float sum = 0.f;
        for (int i = 0; i < EE; ++i)
            if (msk[i] > 0.f) sum += __expf(fmaxf(logits_s[i], 0.f) - mx);
        sm_max = mx;
        sm_sum = sum;
        if (inactive) atomicAdd(&out[FB_OFF], 1.0f);  // integer-valued -> deterministic
    }
    __syncthreads();

    if (tid < EE) {
        float gated = fmaxf(l, 0.f);
        float p = (msk[tid] > 0.f) ? (__expf(gated - sm_max) / sm_sum) : 0.f;
        g_probs_seq[b * EE + tid] = p;
        g_mask_seq[b * EE + tid]  = msk[tid];
        out[LOG_OFF + b * EE + tid] = l;
    }
}

// ---------------------------------------------------------------------------
// Kernel 3: PURE broadcast (no gating, no flags, no spin).
// grid = (BB, TT/TQ) = (32, 16), 256 threads. Loads 512B of per-b results
// into smem, then streams 64 KB of probs + 64 KB of mask per block.
// ---------------------------------------------------------------------------
__global__ void k3_broadcast(float* __restrict__ out) {
    __shared__ float probs_s[EE];
    __shared__ float msk[EE];

    const int b   = blockIdx.x;
    const int yc  = blockIdx.y;
    const int tid = threadIdx.x;

    if (tid < EE) {
        probs_s[tid] = g_probs_seq[b * EE + tid];
        msk[tid]     = g_mask_seq[b * EE + tid];
    }
    __syncthreads();

    const int slot = tid & 15;   // 0..15
    const int trow = tid >> 4;   // 0..15

    const float4 pv = ((const float4*)probs_s)[slot];

    // mask values per slot: slot 0 -> scalars e=0,1,2,63 ; slot s>0 ->
    // aligned float4 at e=4s-1 (MASK_OFF == 1 mod 4)
    float4 mv = make_float4(0.f, 0.f, 0.f, 0.f);
    float m0 = 0.f, m1 = 0.f, m2 = 0.f, m63 = 0.f;
    if (slot == 0) { m0 = msk[0]; m1 = msk[1]; m2 = msk[2]; m63 = msk[63]; }
    else { int e = 4 * slot - 1; mv = make_float4(msk[e], msk[e+1], msk[e+2], msk[e+3]); }

    const size_t brow = (size_t)b * TT * EE;
    const int t0 = yc * TQ;

#pragma unroll
    for (int it = 0; it < TQ / 16; ++it) {
        const size_t row = brow + (size_t)(t0 + it * 16 + trow) * EE;
        __stcs((float4*)(out) + row / 4 + slot, pv);
        if (slot == 0) {
            float* d = out + MASK_OFF + row;
            __stcs(d + 0, m0); __stcs(d + 1, m1); __stcs(d + 2, m2); __stcs(d + 63, m63);
        } else {
            __stcs((float4*)(out + MASK_OFF + row + 4 * slot - 1), mv);
        }
    }
}

// ---------------------------------------------------------------------------
extern "C" void kernel_launch(void* const* d_in, const int* in_sizes, int n_in,
                              void* d_out, int out_size) {
    const float* hs    = (const float*)d_in[0];
    const float* sim   = (const float*)d_in[1];
    const float* gates = (const float*)d_in[2];
    float* out = (float*)d_out;

    k1_partial_sums<<<dim3(C4 / 256, BB, SEG), 256>>>(hs, out);
    k2_gating<<<dim3(PARTS, BB), 256>>>(sim, gates, out);
    k3_broadcast<<<dim3(BB, TT / TQ), 256>>>(out);
}